// round 10
// baseline (speedup 1.0000x reference)
#include <cuda_runtime.h>
#include <cuda_fp16.h>
#include <math.h>

#define N_NODES 100000
#define N_EDGES 1600000
#define NB_SCAN 98          // ceil(100000 / 1024)

// ---------------------------------------------------------------------------
// Scratch (__device__ globals; no allocations anywhere). Kernels receive all
// pointers as parameters (host resolves via cudaGetSymbolAddress).
// ---------------------------------------------------------------------------
__device__ float4 g_agg4[(size_t)N_NODES * 32];   // agg feats / YZ buffer
__device__ float4 g_hA4[(size_t)N_NODES * 32];    // hidden ping / h3
__device__ float4 g_hB4[(size_t)N_NODES * 32];    // hidden pong
__device__ uint2  g_f16_[(size_t)N_NODES * 32];   // fp16 shadow: N x 128 half
                                                  // = N x 32 uint2 (R9 bug: was N*16 -> overflow into g_whi)
__device__ float  g_whi[81920];                   // tf32-hi split weights
__device__ float  g_wlo[81920];                   // tf32-lo split weights
__device__ int    g_row_[N_NODES + 1];            // CSR row starts
__device__ int    g_csr_[N_EDGES];                // CSR col indices (src)
__device__ int    g_bsum_[NB_SCAN];               // scan block sums
__device__ int    g_flag_[1];                     // 1 = int64 edges, 0 = int32

// ---------------------------------------------------------------------------
// Merged weight split for 3xTF32 (all six matrices in one launch).
// hi = top-10-mantissa truncation, lo = residual.
// Layout in whi/wlo: Wl1@0, Wr1@16384, Wl2@32768, Wr2@49152, Wl3@65536, Wr3@73728
// ---------------------------------------------------------------------------
__global__ void w_split_all_kernel(const float* __restrict__ Wl1,
                                   const float* __restrict__ Wr1,
                                   const float* __restrict__ Wl2,
                                   const float* __restrict__ Wr2,
                                   const float* __restrict__ Wl3,
                                   const float* __restrict__ Wr3,
                                   float* __restrict__ hi,
                                   float* __restrict__ lo) {
    int i = blockIdx.x * blockDim.x + threadIdx.x;
    if (i >= 81920) return;
    float v;
    if      (i < 16384) v = Wl1[i];
    else if (i < 32768) v = Wr1[i - 16384];
    else if (i < 49152) v = Wl2[i - 32768];
    else if (i < 65536) v = Wr2[i - 49152];
    else if (i < 73728) v = Wl3[i - 65536];
    else                v = Wr3[i - 73728];
    float h = __uint_as_float(__float_as_uint(v) & 0xFFFFE000u);
    hi[i] = h;
    lo[i] = v - h;
}

// fp32 -> fp16 row conversion (for x before layer-1 gather)
__global__ void f32to16_kernel(const float4* __restrict__ src,
                               __half2* __restrict__ dst, int n4) {
    int i = blockIdx.x * blockDim.x + threadIdx.x;
    if (i < n4) {
        float4 v = src[i];
        dst[2 * i]     = __floats2half2_rn(v.x, v.y);
        dst[2 * i + 1] = __floats2half2_rn(v.z, v.w);
    }
}

// ---------------------------------------------------------------------------
// Edge dtype probe (JAX x64-disabled silently yields int32 despite int64
// annotation).
// ---------------------------------------------------------------------------
__global__ void detect_kernel(const void* __restrict__ ei, int* __restrict__ flag) {
    if (blockIdx.x == 0 && threadIdx.x == 0) {
        const long long* e64 = (const long long*)ei;
        int is64 = 1;
        for (int i = 0; i < 16; i++) {
            long long v = e64[i];
            if (v < 0 || v >= N_NODES) { is64 = 0; break; }
        }
        *flag = is64;
    }
}

__device__ __forceinline__ int2 load_edge(const void* __restrict__ ei, int e, int is64) {
    if (is64) {
        const long long* p = (const long long*)ei;
        return make_int2((int)p[e], (int)p[N_EDGES + e]);
    } else {
        const int* p = (const int*)ei;
        return make_int2(p[e], p[N_EDGES + e]);
    }
}

// ---------------------------------------------------------------------------
// CSR build. Atomics only on harness-allocated d_out scratch.
// ---------------------------------------------------------------------------
__global__ void zero_int_kernel(int* __restrict__ p, int n) {
    int i = blockIdx.x * blockDim.x + threadIdx.x;
    if (i < n) p[i] = 0;
}

__global__ void hist_kernel(const void* __restrict__ ei,
                            const int* __restrict__ flag,
                            int* __restrict__ cnt) {
    int e = blockIdx.x * blockDim.x + threadIdx.x;
    if (e < N_EDGES) {
        int2 sd = load_edge(ei, e, *flag);
        if ((unsigned)sd.x < N_NODES && (unsigned)sd.y < N_NODES)
            atomicAdd(&cnt[sd.y], 1);
    }
}

__global__ void scan_block_kernel(const int* __restrict__ cnt,
                                  int* __restrict__ row,
                                  int* __restrict__ bsum) {
    __shared__ int s[1024];
    int i = blockIdx.x * 1024 + threadIdx.x;
    int v = (i < N_NODES) ? cnt[i] : 0;
    s[threadIdx.x] = v;
    __syncthreads();
    for (int off = 1; off < 1024; off <<= 1) {
        int t = (threadIdx.x >= off) ? s[threadIdx.x - off] : 0;
        __syncthreads();
        s[threadIdx.x] += t;
        __syncthreads();
    }
    if (i < N_NODES) row[i] = s[threadIdx.x] - v;
    if (threadIdx.x == 1023) bsum[blockIdx.x] = s[1023];
}

__global__ void scan_bsum_kernel(int* __restrict__ bsum, int* __restrict__ row) {
    if (threadIdx.x == 0 && blockIdx.x == 0) {
        int acc = 0;
        for (int b = 0; b < NB_SCAN; b++) {
            int t = bsum[b];
            bsum[b] = acc;
            acc += t;
        }
        row[N_NODES] = acc;
    }
}

__global__ void scan_add_kernel(int* __restrict__ row,
                                const int* __restrict__ bsum) {
    int i = blockIdx.x * 1024 + threadIdx.x;
    if (i < N_NODES) row[i] += bsum[blockIdx.x];
}

__global__ void copy_int_kernel(const int* __restrict__ src,
                                int* __restrict__ dst, int n) {
    int i = blockIdx.x * blockDim.x + threadIdx.x;
    if (i < n) dst[i] = src[i];
}

__global__ void fill_kernel(const void* __restrict__ ei,
                            const int* __restrict__ flag,
                            int* __restrict__ cur,
                            int* __restrict__ csr) {
    int e = blockIdx.x * blockDim.x + threadIdx.x;
    if (e < N_EDGES) {
        int2 sd = load_edge(ei, e, *flag);
        if ((unsigned)sd.x < N_NODES && (unsigned)sd.y < N_NODES) {
            int pos = atomicAdd(&cur[sd.y], 1);
            if ((unsigned)pos < N_EDGES) csr[pos] = sd.x;
        }
    }
}

// ---------------------------------------------------------------------------
// Pull-mode aggregation (128-d) from fp16 rows: warp per node, lane owns
// 4 halves (uint2); fp32 accumulate; mean folded in. 256B/row coalesced.
// ---------------------------------------------------------------------------
__device__ __forceinline__ void acc_h4(float4& a, uint2 u) {
    float2 f0 = __half22float2(*(__half2*)&u.x);
    float2 f1 = __half22float2(*(__half2*)&u.y);
    a.x += f0.x; a.y += f0.y; a.z += f1.x; a.w += f1.y;
}

__global__ void gather_kernel(const uint2* __restrict__ f16,
                              const int* __restrict__ row,
                              const int* __restrict__ csr,
                              float4* __restrict__ agg4) {
    int lane = threadIdx.x & 31;
    int n = (blockIdx.x * blockDim.x + threadIdx.x) >> 5;
    if (n >= N_NODES) return;
    int beg = row[n], end = row[n + 1];
    float4 a0 = make_float4(0.f,0.f,0.f,0.f), a1 = a0, a2 = a0, a3 = a0;
    int i = beg;
    for (; i + 3 < end; i += 4) {
        int s0 = csr[i], s1 = csr[i+1], s2 = csr[i+2], s3 = csr[i+3];
        uint2 u0 = f16[(size_t)s0 * 32 + lane];
        uint2 u1 = f16[(size_t)s1 * 32 + lane];
        uint2 u2 = f16[(size_t)s2 * 32 + lane];
        uint2 u3 = f16[(size_t)s3 * 32 + lane];
        acc_h4(a0, u0); acc_h4(a1, u1); acc_h4(a2, u2); acc_h4(a3, u3);
    }
    for (; i < end; i++) {
        uint2 u0 = f16[(size_t)csr[i] * 32 + lane];
        acc_h4(a0, u0);
    }
    a0.x += a1.x + a2.x + a3.x;
    a0.y += a1.y + a2.y + a3.y;
    a0.z += a1.z + a2.z + a3.z;
    a0.w += a1.w + a2.w + a3.w;
    int cnt = end - beg;
    float rd = 1.f / (float)(cnt > 0 ? cnt : 1);
    a0.x *= rd; a0.y *= rd; a0.z *= rd; a0.w *= rd;
    agg4[(size_t)n * 32 + lane] = a0;
}

// ---------------------------------------------------------------------------
// Layer-3 fused gather: h3 = relu( mean_nbr(Y16) + Z ). Half-warp per node;
// Y rows are fp16 (64 halves = 128B), Z read fp32 from YZ buffer.
// ---------------------------------------------------------------------------
__global__ void gather_yz_kernel(const uint2* __restrict__ y16,
                                 const float4* __restrict__ yz4,
                                 const int* __restrict__ row,
                                 const int* __restrict__ csr,
                                 float4* __restrict__ h3_4) {
    int tid = blockIdx.x * blockDim.x + threadIdx.x;
    int n = tid >> 4;
    int l = tid & 15;
    if (n >= N_NODES) return;
    int beg = row[n], end = row[n + 1];
    float4 a0 = make_float4(0.f,0.f,0.f,0.f), a1 = a0;
    int i = beg;
    for (; i + 1 < end; i += 2) {
        uint2 u0 = y16[(size_t)csr[i]   * 16 + l];
        uint2 u1 = y16[(size_t)csr[i+1] * 16 + l];
        acc_h4(a0, u0); acc_h4(a1, u1);
    }
    for (; i < end; i++) {
        uint2 u0 = y16[(size_t)csr[i] * 16 + l];
        acc_h4(a0, u0);
    }
    a0.x += a1.x; a0.y += a1.y; a0.z += a1.z; a0.w += a1.w;
    int cnt = end - beg;
    float rd = 1.f / (float)(cnt > 0 ? cnt : 1);
    float4 z = yz4[(size_t)n * 32 + 16 + l];
    float4 r;
    r.x = fmaxf(a0.x * rd + z.x, 0.f);
    r.y = fmaxf(a0.y * rd + z.y, 0.f);
    r.z = fmaxf(a0.z * rd + z.z, 0.f);
    r.w = fmaxf(a0.w * rd + z.w, 0.f);
    h3_4[(size_t)n * 16 + l] = r;
}

// ---------------------------------------------------------------------------
// 3xTF32 tensor-core GEMM + fp16 dual-write epilogue.
// Non-CAT: writes h fp32 (stride 128) and h fp16 (stride 128 halves).
// CAT: writes YZ fp32; Y cols (<64) also as fp16 rows of 64 halves.
// ---------------------------------------------------------------------------
__device__ __forceinline__ void mma_tf32(float* c, const unsigned* a, const unsigned* b) {
    asm volatile(
        "mma.sync.aligned.m16n8k8.row.col.f32.tf32.tf32.f32 "
        "{%0,%1,%2,%3}, {%4,%5,%6,%7}, {%8,%9}, {%0,%1,%2,%3};\n"
        : "+f"(c[0]), "+f"(c[1]), "+f"(c[2]), "+f"(c[3])
        : "r"(a[0]), "r"(a[1]), "r"(a[2]), "r"(a[3]), "r"(b[0]), "r"(b[1]));
}

template <bool CAT>
__global__ __launch_bounds__(256) void sage_mma_kernel(
    const float* __restrict__ A0,
    const float* __restrict__ A1,
    const float* __restrict__ wh0, const float* __restrict__ wl0,
    const float* __restrict__ wh1, const float* __restrict__ wl1,
    const float* __restrict__ bias,
    float* __restrict__ outp,
    __half* __restrict__ out16)
{
    __shared__ float Ah[128][20], Al[128][20], Wh[128][20], Wlo[128][20];

    const int tid  = threadIdx.x;
    const int lane = tid & 31;
    const int warp = tid >> 5;
    const int wm   = warp & 3;
    const int wn   = warp >> 2;
    const int g    = lane >> 2;
    const int t    = lane & 3;
    const int base = blockIdx.x * 128;

    float c[2][8][4];
#pragma unroll
    for (int mt = 0; mt < 2; mt++)
#pragma unroll
        for (int nt = 0; nt < 8; nt++)
#pragma unroll
            for (int k = 0; k < 4; k++) c[mt][nt][k] = 0.f;

    const int NOPS = CAT ? 1 : 2;
    for (int op = 0; op < NOPS; op++) {
        const float* Ap  = (op == 0) ? A0 : A1;
        const float* Whp = (op == 0) ? wh0 : wh1;
        const float* Wlp = (op == 0) ? wl0 : wl1;
        for (int kc = 0; kc < 8; kc++) {
            const int kb = kc * 16;
            __syncthreads();
#pragma unroll
            for (int it = 0; it < 2; it++) {
                int i = tid + it * 256;
                int r = i >> 2;
                int q = (i & 3) << 2;
                int node = base + r;
                float4 v = make_float4(0.f,0.f,0.f,0.f);
                if (node < N_NODES) v = *(const float4*)(Ap + (size_t)node * 128 + kb + q);
                float4 hv, lv;
                hv.x = __uint_as_float(__float_as_uint(v.x) & 0xFFFFE000u); lv.x = v.x - hv.x;
                hv.y = __uint_as_float(__float_as_uint(v.y) & 0xFFFFE000u); lv.y = v.y - hv.y;
                hv.z = __uint_as_float(__float_as_uint(v.z) & 0xFFFFE000u); lv.z = v.z - hv.z;
                hv.w = __uint_as_float(__float_as_uint(v.w) & 0xFFFFE000u); lv.w = v.w - hv.w;
                *(float4*)&Ah[r][q] = hv;
                *(float4*)&Al[r][q] = lv;
                *(float4*)&Wh[r][q]  = *(const float4*)(Whp + (size_t)r * 128 + kb + q);
                *(float4*)&Wlo[r][q] = *(const float4*)(Wlp + (size_t)r * 128 + kb + q);
            }
            __syncthreads();
#pragma unroll
            for (int ks = 0; ks < 2; ks++) {
                const int kk = ks * 8;
                unsigned ah[2][4], al[2][4];
#pragma unroll
                for (int mt = 0; mt < 2; mt++) {
                    int r0 = wm * 32 + mt * 16 + g;
                    ah[mt][0] = __float_as_uint(Ah[r0    ][kk + t    ]);
                    ah[mt][1] = __float_as_uint(Ah[r0 + 8][kk + t    ]);
                    ah[mt][2] = __float_as_uint(Ah[r0    ][kk + t + 4]);
                    ah[mt][3] = __float_as_uint(Ah[r0 + 8][kk + t + 4]);
                    al[mt][0] = __float_as_uint(Al[r0    ][kk + t    ]);
                    al[mt][1] = __float_as_uint(Al[r0 + 8][kk + t    ]);
                    al[mt][2] = __float_as_uint(Al[r0    ][kk + t + 4]);
                    al[mt][3] = __float_as_uint(Al[r0 + 8][kk + t + 4]);
                }
                unsigned bh[8][2], bl[8][2];
#pragma unroll
                for (int nt = 0; nt < 8; nt++) {
                    int n0 = wn * 64 + nt * 8 + g;
                    bh[nt][0] = __float_as_uint(Wh[n0][kk + t    ]);
                    bh[nt][1] = __float_as_uint(Wh[n0][kk + t + 4]);
                    bl[nt][0] = __float_as_uint(Wlo[n0][kk + t    ]);
                    bl[nt][1] = __float_as_uint(Wlo[n0][kk + t + 4]);
                }
#pragma unroll
                for (int mt = 0; mt < 2; mt++)
#pragma unroll
                    for (int nt = 0; nt < 8; nt++) {
                        mma_tf32(c[mt][nt], ah[mt], bh[nt]);
                        mma_tf32(c[mt][nt], ah[mt], bl[nt]);
                        mma_tf32(c[mt][nt], al[mt], bh[nt]);
                    }
            }
        }
    }

    // epilogue: fp32 + fp16 dual write
#pragma unroll
    for (int mt = 0; mt < 2; mt++) {
        int m0 = base + wm * 32 + mt * 16 + g;
#pragma unroll
        for (int nt = 0; nt < 8; nt++) {
            int n = wn * 64 + nt * 8 + 2 * t;
            float b0, b1;
            if (CAT) {
                b0 = (n     >= 64) ? bias[n     - 64] : 0.f;
                b1 = (n + 1 >= 64) ? bias[n + 1 - 64] : 0.f;
            } else {
                b0 = bias[n]; b1 = bias[n + 1];
            }
            float v0 = c[mt][nt][0] + b0;
            float v1 = c[mt][nt][1] + b1;
            float v2 = c[mt][nt][2] + b0;
            float v3 = c[mt][nt][3] + b1;
            if (!CAT) {
                v0 = fmaxf(v0, 0.f); v1 = fmaxf(v1, 0.f);
                v2 = fmaxf(v2, 0.f); v3 = fmaxf(v3, 0.f);
            }
            if (m0 < N_NODES) {
                *(float2*)(outp + (size_t)m0 * 128 + n) = make_float2(v0, v1);
                if (!CAT)
                    *(__half2*)(out16 + (size_t)m0 * 128 + n) = __floats2half2_rn(v0, v1);
                else if (n < 64)
                    *(__half2*)(out16 + (size_t)m0 * 64 + n) = __floats2half2_rn(v0, v1);
            }
            if (m0 + 8 < N_NODES) {
                *(float2*)(outp + (size_t)(m0 + 8) * 128 + n) = make_float2(v2, v3);
                if (!CAT)
                    *(__half2*)(out16 + (size_t)(m0 + 8) * 128 + n) = __floats2half2_rn(v2, v3);
                else if (n < 64)
                    *(__half2*)(out16 + (size_t)(m0 + 8) * 64 + n) = __floats2half2_rn(v2, v3);
            }
        }
    }
}

// ---------------------------------------------------------------------------
// Classifier: sigmoid(h3 @ Wc^T + bc). Warp per node, 2 features/lane.
// ---------------------------------------------------------------------------
__global__ void cls_kernel(const float* __restrict__ h,
                           const float* __restrict__ Wc,
                           const float* __restrict__ bc,
                           float* __restrict__ outp) {
    int lane = threadIdx.x & 31;
    int n = (blockIdx.x * blockDim.x + threadIdx.x) >> 5;
    if (n >= N_NODES) return;
    float w0 = Wc[lane * 2], w1 = Wc[lane * 2 + 1];
    float b = bc[0];
    const float* hp = h + (size_t)n * 64 + lane * 2;
    float s = hp[0] * w0 + hp[1] * w1;
#pragma unroll
    for (int o = 16; o > 0; o >>= 1) s += __shfl_xor_sync(0xffffffffu, s, o);
    if (lane == 0) outp[n] = 1.f / (1.f + expf(-(s + b)));
}

// ---------------------------------------------------------------------------
// Launch. d_out doubles as int scratch during CSR build, overwritten at end.
// ---------------------------------------------------------------------------
extern "C" void kernel_launch(void* const* d_in, const int* in_sizes, int n_in,
                              void* d_out, int out_size) {
    const float* x   = (const float*)d_in[0];
    const void*  ei  = d_in[1];               // int32 or int64, probed at runtime
    const float* Wl1 = (const float*)d_in[2];
    const float* bl1 = (const float*)d_in[3];
    const float* Wr1 = (const float*)d_in[4];
    const float* Wl2 = (const float*)d_in[5];
    const float* bl2 = (const float*)d_in[6];
    const float* Wr2 = (const float*)d_in[7];
    const float* Wl3 = (const float*)d_in[8];
    const float* bl3 = (const float*)d_in[9];
    const float* Wr3 = (const float*)d_in[10];
    const float* Wc  = (const float*)d_in[11];
    const float* bc  = (const float*)d_in[12];

    void *p_agg=0, *p_hA=0, *p_hB=0, *p_f16=0, *p_row=0, *p_csr=0, *p_bsum=0, *p_flag=0, *p_whi=0, *p_wlo=0;
    cudaGetSymbolAddress(&p_agg,  g_agg4);
    cudaGetSymbolAddress(&p_hA,   g_hA4);
    cudaGetSymbolAddress(&p_hB,   g_hB4);
    cudaGetSymbolAddress(&p_f16,  g_f16_);
    cudaGetSymbolAddress(&p_row,  g_row_);
    cudaGetSymbolAddress(&p_csr,  g_csr_);
    cudaGetSymbolAddress(&p_bsum, g_bsum_);
    cudaGetSymbolAddress(&p_flag, g_flag_);
    cudaGetSymbolAddress(&p_whi,  g_whi);
    cudaGetSymbolAddress(&p_wlo,  g_wlo);

    float4* agg4 = (float4*)p_agg;
    float4* hA4  = (float4*)p_hA;
    float*  aggf = (float*)p_agg;
    float*  hAf  = (float*)p_hA;
    float*  hBf  = (float*)p_hB;
    uint2*  f16  = (uint2*)p_f16;
    __half* f16h = (__half*)p_f16;
    float*  whi  = (float*)p_whi;
    float*  wlo  = (float*)p_wlo;
    int*    row  = (int*)p_row;
    int*    csr  = (int*)p_csr;
    int*    bsum = (int*)p_bsum;
    int*    flag = (int*)p_flag;
    int*    scr  = (int*)d_out;
    float*  out  = (float*)d_out;

    const int EB  = (N_EDGES + 255) / 256;
    const int NB  = (N_NODES + 255) / 256;
    const int WNB = (N_NODES * 32 + 255) / 256;       // warp per node
    const int HNB = (N_NODES * 16 + 255) / 256;       // half-warp per node
    const int GMB = (N_NODES + 127) / 128;            // 128-node GEMM tiles
    const int C4B = (N_NODES * 32 + 255) / 256;       // x convert (float4 units)

    // weight splits (one launch) + x fp16 conversion
    w_split_all_kernel<<<320, 256>>>(Wl1, Wr1, Wl2, Wr2, Wl3, Wr3, whi, wlo);
    f32to16_kernel<<<C4B, 256>>>((const float4*)x, (__half2*)f16h, N_NODES * 32);

    // edge dtype probe + CSR build (atomics only on scr / d_out)
    detect_kernel<<<1, 32>>>(ei, flag);
    zero_int_kernel<<<NB, 256>>>(scr, N_NODES);
    hist_kernel<<<EB, 256>>>(ei, flag, scr);
    scan_block_kernel<<<NB_SCAN, 1024>>>(scr, row, bsum);
    scan_bsum_kernel<<<1, 32>>>(bsum, row);
    scan_add_kernel<<<NB_SCAN, 1024>>>(row, bsum);
    copy_int_kernel<<<NB, 256>>>(row, scr, N_NODES);
    fill_kernel<<<EB, 256>>>(ei, flag, scr, csr);

    // layer 1: gather(x16) -> agg; GEMM(agg, x) -> hA fp32 + h1 fp16
    gather_kernel<<<WNB, 256>>>(f16, row, csr, agg4);
    sage_mma_kernel<false><<<GMB, 256>>>(aggf, x, whi + 0, wlo + 0,
                                         whi + 16384, wlo + 16384, bl1, hAf, f16h);

    // layer 2: gather(h1_16) -> agg; GEMM(agg, hA) -> hB fp32 + h2 fp16
    gather_kernel<<<WNB, 256>>>(f16, row, csr, agg4);
    sage_mma_kernel<false><<<GMB, 256>>>(aggf, hAf, whi + 32768, wlo + 32768,
                                         whi + 49152, wlo + 49152, bl2, hBf, f16h);

    // layer 3: YZ = h2 @ [Wl3;Wr3]^T (Y fp16 dual-write), then fused gather
    sage_mma_kernel<true><<<GMB, 256>>>(hBf, hBf, whi + 65536, wlo + 65536,
                                        whi + 65536, wlo + 65536, bl3, aggf, f16h);
    gather_yz_kernel<<<HNB, 256>>>(f16, agg4, row, csr, hA4);

    // classifier overwrites d_out
    cls_kernel<<<WNB, 256>>>(hAf, Wc, bc, out);
}

// round 11
// speedup vs baseline: 1.0341x; 1.0341x over previous
#include <cuda_runtime.h>
#include <cuda_fp16.h>
#include <math.h>

#define N_NODES 100000
#define N_EDGES 1600000
#define NB_SCAN 98          // ceil(100000 / 1024)

// ---------------------------------------------------------------------------
// Scratch (__device__ globals; no allocations anywhere). Kernels receive all
// pointers as parameters (host resolves via cudaGetSymbolAddress).
// ---------------------------------------------------------------------------
__device__ float4 g_agg4[(size_t)N_NODES * 32];   // agg feats / YZ buffer
__device__ float4 g_hA4[(size_t)N_NODES * 32];    // hidden ping / h3
__device__ float4 g_hB4[(size_t)N_NODES * 32];    // hidden pong
__device__ uint4  g_f16_[(size_t)N_NODES * 16];   // fp16 shadow: N x 128 half = N x 16 uint4
__device__ float  g_whi[81920];                   // tf32-hi split weights
__device__ float  g_wlo[81920];                   // tf32-lo split weights
__device__ int    g_row_[N_NODES + 1];            // CSR row starts
__device__ int    g_csr_[N_EDGES];                // CSR col indices (src)
__device__ int    g_bsum_[NB_SCAN];               // scan block sums
__device__ int    g_flag_[1];                     // 1 = int64 edges, 0 = int32

// ---------------------------------------------------------------------------
// Merged weight split for 3xTF32 (all six matrices in one launch).
// Layout in whi/wlo: Wl1@0, Wr1@16384, Wl2@32768, Wr2@49152, Wl3@65536, Wr3@73728
// ---------------------------------------------------------------------------
__global__ void w_split_all_kernel(const float* __restrict__ Wl1,
                                   const float* __restrict__ Wr1,
                                   const float* __restrict__ Wl2,
                                   const float* __restrict__ Wr2,
                                   const float* __restrict__ Wl3,
                                   const float* __restrict__ Wr3,
                                   float* __restrict__ hi,
                                   float* __restrict__ lo) {
    int i = blockIdx.x * blockDim.x + threadIdx.x;
    if (i >= 81920) return;
    float v;
    if      (i < 16384) v = Wl1[i];
    else if (i < 32768) v = Wr1[i - 16384];
    else if (i < 49152) v = Wl2[i - 32768];
    else if (i < 65536) v = Wr2[i - 49152];
    else if (i < 73728) v = Wl3[i - 65536];
    else                v = Wr3[i - 73728];
    float h = __uint_as_float(__float_as_uint(v) & 0xFFFFE000u);
    hi[i] = h;
    lo[i] = v - h;
}

// fp32 -> fp16 row conversion (for x before layer-1 gather)
__global__ void f32to16_kernel(const float4* __restrict__ src,
                               __half2* __restrict__ dst, int n4) {
    int i = blockIdx.x * blockDim.x + threadIdx.x;
    if (i < n4) {
        float4 v = src[i];
        dst[2 * i]     = __floats2half2_rn(v.x, v.y);
        dst[2 * i + 1] = __floats2half2_rn(v.z, v.w);
    }
}

// ---------------------------------------------------------------------------
// Edge dtype probe (JAX x64-disabled silently yields int32 despite int64
// annotation).
// ---------------------------------------------------------------------------
__global__ void detect_kernel(const void* __restrict__ ei, int* __restrict__ flag) {
    if (blockIdx.x == 0 && threadIdx.x == 0) {
        const long long* e64 = (const long long*)ei;
        int is64 = 1;
        for (int i = 0; i < 16; i++) {
            long long v = e64[i];
            if (v < 0 || v >= N_NODES) { is64 = 0; break; }
        }
        *flag = is64;
    }
}

__device__ __forceinline__ int2 load_edge(const void* __restrict__ ei, int e, int is64) {
    if (is64) {
        const long long* p = (const long long*)ei;
        return make_int2((int)p[e], (int)p[N_EDGES + e]);
    } else {
        const int* p = (const int*)ei;
        return make_int2(p[e], p[N_EDGES + e]);
    }
}

// ---------------------------------------------------------------------------
// CSR build. Atomics only on harness-allocated d_out scratch.
// ---------------------------------------------------------------------------
__global__ void zero_int_kernel(int* __restrict__ p, int n) {
    int i = blockIdx.x * blockDim.x + threadIdx.x;
    if (i < n) p[i] = 0;
}

__global__ void hist_kernel(const void* __restrict__ ei,
                            const int* __restrict__ flag,
                            int* __restrict__ cnt) {
    int e = blockIdx.x * blockDim.x + threadIdx.x;
    if (e < N_EDGES) {
        int2 sd = load_edge(ei, e, *flag);
        if ((unsigned)sd.x < N_NODES && (unsigned)sd.y < N_NODES)
            atomicAdd(&cnt[sd.y], 1);
    }
}

__global__ void scan_block_kernel(const int* __restrict__ cnt,
                                  int* __restrict__ row,
                                  int* __restrict__ bsum) {
    __shared__ int s[1024];
    int i = blockIdx.x * 1024 + threadIdx.x;
    int v = (i < N_NODES) ? cnt[i] : 0;
    s[threadIdx.x] = v;
    __syncthreads();
    for (int off = 1; off < 1024; off <<= 1) {
        int t = (threadIdx.x >= off) ? s[threadIdx.x - off] : 0;
        __syncthreads();
        s[threadIdx.x] += t;
        __syncthreads();
    }
    if (i < N_NODES) row[i] = s[threadIdx.x] - v;
    if (threadIdx.x == 1023) bsum[blockIdx.x] = s[1023];
}

__global__ void scan_bsum_kernel(int* __restrict__ bsum, int* __restrict__ row) {
    if (threadIdx.x == 0 && blockIdx.x == 0) {
        int acc = 0;
        for (int b = 0; b < NB_SCAN; b++) {
            int t = bsum[b];
            bsum[b] = acc;
            acc += t;
        }
        row[N_NODES] = acc;
    }
}

// stage 3: add block offsets; also seed fill cursors (drops copy kernel)
__global__ void scan_add_kernel(int* __restrict__ row,
                                const int* __restrict__ bsum,
                                int* __restrict__ cur) {
    int i = blockIdx.x * 1024 + threadIdx.x;
    if (i < N_NODES) {
        int v = row[i] + bsum[blockIdx.x];
        row[i] = v;
        cur[i] = v;
    }
}

__global__ void fill_kernel(const void* __restrict__ ei,
                            const int* __restrict__ flag,
                            int* __restrict__ cur,
                            int* __restrict__ csr) {
    int e = blockIdx.x * blockDim.x + threadIdx.x;
    if (e < N_EDGES) {
        int2 sd = load_edge(ei, e, *flag);
        if ((unsigned)sd.x < N_NODES && (unsigned)sd.y < N_NODES) {
            int pos = atomicAdd(&cur[sd.y], 1);
            if ((unsigned)pos < N_EDGES) csr[pos] = sd.x;
        }
    }
}

// ---------------------------------------------------------------------------
// Pull-mode aggregation (128-d) from fp16 rows: HALF-WARP per node.
// Row = 256B = 16 lanes x uint4 -> one warp-LDG services TWO edges.
// fp32 accumulate; mean folded in.
// ---------------------------------------------------------------------------
__device__ __forceinline__ void acc8(float* a, uint4 u) {
    float2 f0 = __half22float2(*(__half2*)&u.x);
    float2 f1 = __half22float2(*(__half2*)&u.y);
    float2 f2 = __half22float2(*(__half2*)&u.z);
    float2 f3 = __half22float2(*(__half2*)&u.w);
    a[0] += f0.x; a[1] += f0.y; a[2] += f1.x; a[3] += f1.y;
    a[4] += f2.x; a[5] += f2.y; a[6] += f3.x; a[7] += f3.y;
}

__global__ void gather_kernel(const uint4* __restrict__ f16,
                              const int* __restrict__ row,
                              const int* __restrict__ csr,
                              float4* __restrict__ agg4) {
    int tid = blockIdx.x * blockDim.x + threadIdx.x;
    int n = tid >> 4;          // half-warp per node
    int l = tid & 15;
    if (n >= N_NODES) return;
    int beg = row[n], end = row[n + 1];
    float a[8] = {0,0,0,0,0,0,0,0};
    float b[8] = {0,0,0,0,0,0,0,0};
    int i = beg;
    for (; i + 3 < end; i += 4) {
        uint4 u0 = f16[(size_t)csr[i]   * 16 + l];
        uint4 u1 = f16[(size_t)csr[i+1] * 16 + l];
        uint4 u2 = f16[(size_t)csr[i+2] * 16 + l];
        uint4 u3 = f16[(size_t)csr[i+3] * 16 + l];
        acc8(a, u0); acc8(b, u1); acc8(a, u2); acc8(b, u3);
    }
    for (; i < end; i++) {
        uint4 u0 = f16[(size_t)csr[i] * 16 + l];
        acc8(a, u0);
    }
#pragma unroll
    for (int k = 0; k < 8; k++) a[k] += b[k];
    int cnt = end - beg;
    float rd = 1.f / (float)(cnt > 0 ? cnt : 1);
#pragma unroll
    for (int k = 0; k < 8; k++) a[k] *= rd;
    // lane l holds feats [8l, 8l+8) -> two float4 stores
    agg4[(size_t)n * 32 + 2 * l]     = make_float4(a[0], a[1], a[2], a[3]);
    agg4[(size_t)n * 32 + 2 * l + 1] = make_float4(a[4], a[5], a[6], a[7]);
}

// ---------------------------------------------------------------------------
// Layer-3 fused gather: h3 = relu( mean_nbr(Y16) + Z ). QUARTER-warp per
// node: Y row = 128B = 8 lanes x uint4 -> one warp-LDG services FOUR edges.
// ---------------------------------------------------------------------------
__global__ void gather_yz_kernel(const uint4* __restrict__ y16,
                                 const float4* __restrict__ yz4,
                                 const int* __restrict__ row,
                                 const int* __restrict__ csr,
                                 float4* __restrict__ h3_4) {
    int tid = blockIdx.x * blockDim.x + threadIdx.x;
    int n = tid >> 3;          // quarter-warp per node
    int l = tid & 7;
    if (n >= N_NODES) return;
    int beg = row[n], end = row[n + 1];
    float a[8] = {0,0,0,0,0,0,0,0};
    float b[8] = {0,0,0,0,0,0,0,0};
    int i = beg;
    for (; i + 3 < end; i += 4) {
        uint4 u0 = y16[(size_t)csr[i]   * 8 + l];
        uint4 u1 = y16[(size_t)csr[i+1] * 8 + l];
        uint4 u2 = y16[(size_t)csr[i+2] * 8 + l];
        uint4 u3 = y16[(size_t)csr[i+3] * 8 + l];
        acc8(a, u0); acc8(b, u1); acc8(a, u2); acc8(b, u3);
    }
    for (; i < end; i++) {
        uint4 u0 = y16[(size_t)csr[i] * 8 + l];
        acc8(a, u0);
    }
#pragma unroll
    for (int k = 0; k < 8; k++) a[k] += b[k];
    int cnt = end - beg;
    float rd = 1.f / (float)(cnt > 0 ? cnt : 1);
    // Z = cols 64..127 of the fp32 YZ row (float4 idx 16 + 2l, 17 + 2l)
    float4 z0 = yz4[(size_t)n * 32 + 16 + 2 * l];
    float4 z1 = yz4[(size_t)n * 32 + 17 + 2 * l];
    float4 r0, r1;
    r0.x = fmaxf(a[0] * rd + z0.x, 0.f);
    r0.y = fmaxf(a[1] * rd + z0.y, 0.f);
    r0.z = fmaxf(a[2] * rd + z0.z, 0.f);
    r0.w = fmaxf(a[3] * rd + z0.w, 0.f);
    r1.x = fmaxf(a[4] * rd + z1.x, 0.f);
    r1.y = fmaxf(a[5] * rd + z1.y, 0.f);
    r1.z = fmaxf(a[6] * rd + z1.z, 0.f);
    r1.w = fmaxf(a[7] * rd + z1.w, 0.f);
    h3_4[(size_t)n * 16 + 2 * l]     = r0;
    h3_4[(size_t)n * 16 + 2 * l + 1] = r1;
}

// ---------------------------------------------------------------------------
// 3xTF32 tensor-core GEMM + fp16 dual-write epilogue (unchanged from R10).
// ---------------------------------------------------------------------------
__device__ __forceinline__ void mma_tf32(float* c, const unsigned* a, const unsigned* b) {
    asm volatile(
        "mma.sync.aligned.m16n8k8.row.col.f32.tf32.tf32.f32 "
        "{%0,%1,%2,%3}, {%4,%5,%6,%7}, {%8,%9}, {%0,%1,%2,%3};\n"
        : "+f"(c[0]), "+f"(c[1]), "+f"(c[2]), "+f"(c[3])
        : "r"(a[0]), "r"(a[1]), "r"(a[2]), "r"(a[3]), "r"(b[0]), "r"(b[1]));
}

template <bool CAT>
__global__ __launch_bounds__(256) void sage_mma_kernel(
    const float* __restrict__ A0,
    const float* __restrict__ A1,
    const float* __restrict__ wh0, const float* __restrict__ wl0,
    const float* __restrict__ wh1, const float* __restrict__ wl1,
    const float* __restrict__ bias,
    float* __restrict__ outp,
    __half* __restrict__ out16)
{
    __shared__ float Ah[128][20], Al[128][20], Wh[128][20], Wlo[128][20];

    const int tid  = threadIdx.x;
    const int lane = tid & 31;
    const int warp = tid >> 5;
    const int wm   = warp & 3;
    const int wn   = warp >> 2;
    const int g    = lane >> 2;
    const int t    = lane & 3;
    const int base = blockIdx.x * 128;

    float c[2][8][4];
#pragma unroll
    for (int mt = 0; mt < 2; mt++)
#pragma unroll
        for (int nt = 0; nt < 8; nt++)
#pragma unroll
            for (int k = 0; k < 4; k++) c[mt][nt][k] = 0.f;

    const int NOPS = CAT ? 1 : 2;
    for (int op = 0; op < NOPS; op++) {
        const float* Ap  = (op == 0) ? A0 : A1;
        const float* Whp = (op == 0) ? wh0 : wh1;
        const float* Wlp = (op == 0) ? wl0 : wl1;
        for (int kc = 0; kc < 8; kc++) {
            const int kb = kc * 16;
            __syncthreads();
#pragma unroll
            for (int it = 0; it < 2; it++) {
                int i = tid + it * 256;
                int r = i >> 2;
                int q = (i & 3) << 2;
                int node = base + r;
                float4 v = make_float4(0.f,0.f,0.f,0.f);
                if (node < N_NODES) v = *(const float4*)(Ap + (size_t)node * 128 + kb + q);
                float4 hv, lv;
                hv.x = __uint_as_float(__float_as_uint(v.x) & 0xFFFFE000u); lv.x = v.x - hv.x;
                hv.y = __uint_as_float(__float_as_uint(v.y) & 0xFFFFE000u); lv.y = v.y - hv.y;
                hv.z = __uint_as_float(__float_as_uint(v.z) & 0xFFFFE000u); lv.z = v.z - hv.z;
                hv.w = __uint_as_float(__float_as_uint(v.w) & 0xFFFFE000u); lv.w = v.w - hv.w;
                *(float4*)&Ah[r][q] = hv;
                *(float4*)&Al[r][q] = lv;
                *(float4*)&Wh[r][q]  = *(const float4*)(Whp + (size_t)r * 128 + kb + q);
                *(float4*)&Wlo[r][q] = *(const float4*)(Wlp + (size_t)r * 128 + kb + q);
            }
            __syncthreads();
#pragma unroll
            for (int ks = 0; ks < 2; ks++) {
                const int kk = ks * 8;
                unsigned ah[2][4], al[2][4];
#pragma unroll
                for (int mt = 0; mt < 2; mt++) {
                    int r0 = wm * 32 + mt * 16 + g;
                    ah[mt][0] = __float_as_uint(Ah[r0    ][kk + t    ]);
                    ah[mt][1] = __float_as_uint(Ah[r0 + 8][kk + t    ]);
                    ah[mt][2] = __float_as_uint(Ah[r0    ][kk + t + 4]);
                    ah[mt][3] = __float_as_uint(Ah[r0 + 8][kk + t + 4]);
                    al[mt][0] = __float_as_uint(Al[r0    ][kk + t    ]);
                    al[mt][1] = __float_as_uint(Al[r0 + 8][kk + t    ]);
                    al[mt][2] = __float_as_uint(Al[r0    ][kk + t + 4]);
                    al[mt][3] = __float_as_uint(Al[r0 + 8][kk + t + 4]);
                }
                unsigned bh[8][2], bl[8][2];
#pragma unroll
                for (int nt = 0; nt < 8; nt++) {
                    int n0 = wn * 64 + nt * 8 + g;
                    bh[nt][0] = __float_as_uint(Wh[n0][kk + t    ]);
                    bh[nt][1] = __float_as_uint(Wh[n0][kk + t + 4]);
                    bl[nt][0] = __float_as_uint(Wlo[n0][kk + t    ]);
                    bl[nt][1] = __float_as_uint(Wlo[n0][kk + t + 4]);
                }
#pragma unroll
                for (int mt = 0; mt < 2; mt++)
#pragma unroll
                    for (int nt = 0; nt < 8; nt++) {
                        mma_tf32(c[mt][nt], ah[mt], bh[nt]);
                        mma_tf32(c[mt][nt], ah[mt], bl[nt]);
                        mma_tf32(c[mt][nt], al[mt], bh[nt]);
                    }
            }
        }
    }

    // epilogue: fp32 + fp16 dual write
#pragma unroll
    for (int mt = 0; mt < 2; mt++) {
        int m0 = base + wm * 32 + mt * 16 + g;
#pragma unroll
        for (int nt = 0; nt < 8; nt++) {
            int n = wn * 64 + nt * 8 + 2 * t;
            float b0, b1;
            if (CAT) {
                b0 = (n     >= 64) ? bias[n     - 64] : 0.f;
                b1 = (n + 1 >= 64) ? bias[n + 1 - 64] : 0.f;
            } else {
                b0 = bias[n]; b1 = bias[n + 1];
            }
            float v0 = c[mt][nt][0] + b0;
            float v1 = c[mt][nt][1] + b1;
            float v2 = c[mt][nt][2] + b0;
            float v3 = c[mt][nt][3] + b1;
            if (!CAT) {
                v0 = fmaxf(v0, 0.f); v1 = fmaxf(v1, 0.f);
                v2 = fmaxf(v2, 0.f); v3 = fmaxf(v3, 0.f);
            }
            if (m0 < N_NODES) {
                *(float2*)(outp + (size_t)m0 * 128 + n) = make_float2(v0, v1);
                if (!CAT)
                    *(__half2*)(out16 + (size_t)m0 * 128 + n) = __floats2half2_rn(v0, v1);
                else if (n < 64)
                    *(__half2*)(out16 + (size_t)m0 * 64 + n) = __floats2half2_rn(v0, v1);
            }
            if (m0 + 8 < N_NODES) {
                *(float2*)(outp + (size_t)(m0 + 8) * 128 + n) = make_float2(v2, v3);
                if (!CAT)
                    *(__half2*)(out16 + (size_t)(m0 + 8) * 128 + n) = __floats2half2_rn(v2, v3);
                else if (n < 64)
                    *(__half2*)(out16 + (size_t)(m0 + 8) * 64 + n) = __floats2half2_rn(v2, v3);
            }
        }
    }
}

// ---------------------------------------------------------------------------
// Classifier: sigmoid(h3 @ Wc^T + bc). Warp per node, 2 features/lane.
// ---------------------------------------------------------------------------
__global__ void cls_kernel(const float* __restrict__ h,
                           const float* __restrict__ Wc,
                           const float* __restrict__ bc,
                           float* __restrict__ outp) {
    int lane = threadIdx.x & 31;
    int n = (blockIdx.x * blockDim.x + threadIdx.x) >> 5;
    if (n >= N_NODES) return;
    float w0 = Wc[lane * 2], w1 = Wc[lane * 2 + 1];
    float b = bc[0];
    const float* hp = h + (size_t)n * 64 + lane * 2;
    float s = hp[0] * w0 + hp[1] * w1;
#pragma unroll
    for (int o = 16; o > 0; o >>= 1) s += __shfl_xor_sync(0xffffffffu, s, o);
    if (lane == 0) outp[n] = 1.f / (1.f + expf(-(s + b)));
}

// ---------------------------------------------------------------------------
// Launch. d_out doubles as int scratch during CSR build, overwritten at end.
// ---------------------------------------------------------------------------
extern "C" void kernel_launch(void* const* d_in, const int* in_sizes, int n_in,
                              void* d_out, int out_size) {
    const float* x   = (const float*)d_in[0];
    const void*  ei  = d_in[1];               // int32 or int64, probed at runtime
    const float* Wl1 = (const float*)d_in[2];
    const float* bl1 = (const float*)d_in[3];
    const float* Wr1 = (const float*)d_in[4];
    const float* Wl2 = (const float*)d_in[5];
    const float* bl2 = (const float*)d_in[6];
    const float* Wr2 = (const float*)d_in[7];
    const float* Wl3 = (const float*)d_in[8];
    const float* bl3 = (const float*)d_in[9];
    const float* Wr3 = (const float*)d_in[10];
    const float* Wc  = (const float*)d_in[11];
    const float* bc  = (const float*)d_in[12];

    void *p_agg=0, *p_hA=0, *p_hB=0, *p_f16=0, *p_row=0, *p_csr=0, *p_bsum=0, *p_flag=0, *p_whi=0, *p_wlo=0;
    cudaGetSymbolAddress(&p_agg,  g_agg4);
    cudaGetSymbolAddress(&p_hA,   g_hA4);
    cudaGetSymbolAddress(&p_hB,   g_hB4);
    cudaGetSymbolAddress(&p_f16,  g_f16_);
    cudaGetSymbolAddress(&p_row,  g_row_);
    cudaGetSymbolAddress(&p_csr,  g_csr_);
    cudaGetSymbolAddress(&p_bsum, g_bsum_);
    cudaGetSymbolAddress(&p_flag, g_flag_);
    cudaGetSymbolAddress(&p_whi,  g_whi);
    cudaGetSymbolAddress(&p_wlo,  g_wlo);

    float4* agg4 = (float4*)p_agg;
    float4* hA4  = (float4*)p_hA;
    float*  aggf = (float*)p_agg;
    float*  hAf  = (float*)p_hA;
    float*  hBf  = (float*)p_hB;
    uint4*  f16  = (uint4*)p_f16;
    __half* f16h = (__half*)p_f16;
    float*  whi  = (float*)p_whi;
    float*  wlo  = (float*)p_wlo;
    int*    row  = (int*)p_row;
    int*    csr  = (int*)p_csr;
    int*    bsum = (int*)p_bsum;
    int*    flag = (int*)p_flag;
    int*    scr  = (int*)d_out;
    float*  out  = (float*)d_out;

    const int EB  = (N_EDGES + 255) / 256;
    const int NB  = (N_NODES + 255) / 256;
    const int WNB = (N_NODES * 32 + 255) / 256;       // warp per node (cls)
    const int HWB = (N_NODES * 16 + 255) / 256;       // half-warp per node
    const int QWB = (N_NODES * 8 + 255) / 256;        // quarter-warp per node
    const int GMB = (N_NODES + 127) / 128;            // 128-node GEMM tiles
    const int C4B = (N_NODES * 32 + 255) / 256;       // x convert (float4 units)

    // weight splits (one launch) + x fp16 conversion
    w_split_all_kernel<<<320, 256>>>(Wl1, Wr1, Wl2, Wr2, Wl3, Wr3, whi, wlo);
    f32to16_kernel<<<C4B, 256>>>((const float4*)x, (__half2*)f16h, N_NODES * 32);

    // edge dtype probe + CSR build (atomics only on scr / d_out)
    detect_kernel<<<1, 32>>>(ei, flag);
    zero_int_kernel<<<NB, 256>>>(scr, N_NODES);
    hist_kernel<<<EB, 256>>>(ei, flag, scr);
    scan_block_kernel<<<NB_SCAN, 1024>>>(scr, row, bsum);
    scan_bsum_kernel<<<1, 32>>>(bsum, row);
    scan_add_kernel<<<NB_SCAN, 1024>>>(row, bsum, scr);
    fill_kernel<<<EB, 256>>>(ei, flag, scr, csr);

    // layer 1: gather(x16) -> agg; GEMM(agg, x) -> hA fp32 + h1 fp16
    gather_kernel<<<HWB, 256>>>(f16, row, csr, agg4);
    sage_mma_kernel<false><<<GMB, 256>>>(aggf, x, whi + 0, wlo + 0,
                                         whi + 16384, wlo + 16384, bl1, hAf, f16h);

    // layer 2: gather(h1_16) -> agg; GEMM(agg, hA) -> hB fp32 + h2 fp16
    gather_kernel<<<HWB, 256>>>(f16, row, csr, agg4);
    sage_mma_kernel<false><<<GMB, 256>>>(aggf, hAf, whi + 32768, wlo + 32768,
                                         whi + 49152, wlo + 49152, bl2, hBf, f16h);

    // layer 3: YZ = h2 @ [Wl3;Wr3]^T (Y fp16 dual-write), then fused gather
    sage_mma_kernel<true><<<GMB, 256>>>(hBf, hBf, whi + 65536, wlo + 65536,
                                        whi + 65536, wlo + 65536, bl3, aggf, f16h);
    gather_yz_kernel<<<QWB, 256>>>(f16, agg4, row, csr, hA4);

    // classifier overwrites d_out
    cls_kernel<<<WNB, 256>>>(hAf, Wc, bc, out);
}